// round 8
// baseline (speedup 1.0000x reference)
#include <cuda_runtime.h>
#include <cuda_bf16.h>
#include <cstdint>

// Problem constants (fixed by reference setup_inputs)
#define Bq     4
#define NPIX   4096          // 64*64
#define HEADS  8
#define HD     64
#define DIMM   512
#define INNER  512           // HEADS*HD
#define MROWS  (Bq*NPIX)     // 16384
#define QKV_N  (3*INNER)     // 1536

// Scratch (device globals — no runtime allocation allowed)
// g_qkv holds qkvT: [1536 dims][16384 rows]  (dim-major!)
__device__ float g_qkv[(size_t)MROWS * QKV_N];   // ~100.7 MB
__device__ float g_att[(size_t)MROWS * INNER];   // ~33.5 MB (pixel-major)

// ---------------------------------------------------------------------------
// Warp-level tensor-core primitives (base PTX — compile at compute_103)
// ---------------------------------------------------------------------------
__device__ __forceinline__ uint32_t smem_u32(const void* p) {
    uint32_t a;
    asm("{ .reg .u64 t; cvta.to.shared.u64 t, %1; cvt.u32.u64 %0, t; }"
        : "=r"(a) : "l"(p));
    return a;
}
__device__ __forceinline__ void ldm_x4(uint32_t* r, uint32_t addr) {
    asm volatile("ldmatrix.sync.aligned.m8n8.x4.shared.b16 {%0,%1,%2,%3}, [%4];"
                 : "=r"(r[0]), "=r"(r[1]), "=r"(r[2]), "=r"(r[3]) : "r"(addr));
}
__device__ __forceinline__ void mma16816(float* d, const uint32_t* a,
                                         uint32_t b0, uint32_t b1) {
    asm volatile(
        "mma.sync.aligned.m16n8k16.row.col.f32.bf16.bf16.f32 "
        "{%0,%1,%2,%3}, {%4,%5,%6,%7}, {%8,%9}, {%0,%1,%2,%3};"
        : "+f"(d[0]), "+f"(d[1]), "+f"(d[2]), "+f"(d[3])
        : "r"(a[0]), "r"(a[1]), "r"(a[2]), "r"(a[3]), "r"(b0), "r"(b1));
}
#define SMEM_SWIZZLE_128B(b) ((b) ^ (((b) >> 3) & 0x70))

// ---------------------------------------------------------------------------
// bf16-split GEMM via mma.sync: C[M,N] = A[M,K] @ B[N,K]^T (+ bias[N]).
// fp32 -> bf16 hi+lo; D = Ah*Bh + Ah*Bl + Al*Bh, fp32 accumulate.
// CTA 128x128, 256 threads (8 warps: 4 M x 2 N, warp tile 32x64), BK=64.
// TSTORE: write C transposed as C_T[col][row] with row-stride MROWS (=16384).
// ---------------------------------------------------------------------------
#define G_BK     64
#define TILE_B   16384                      // one 128x64 bf16 tile
#define SM_A_HI  0
#define SM_A_LO  16384
#define SM_B_HI  32768
#define SM_B_LO  49152
#define SM_TOTAL 65536

__device__ __forceinline__ void load_split_tile(
    const float* __restrict__ src, int K, int k0,
    char* smem, int off_hi, int off_lo, int tid)
{
#pragma unroll
    for (int i = 0; i < 4; i++) {
        const int idx = tid + 256 * i;   // 0..1023 chunk id
        const int row = idx >> 3;
        const int cc  = idx & 7;
        const float4* gp = reinterpret_cast<const float4*>(
            src + (size_t)row * K + k0 + cc * 8);
        float4 f0 = gp[0];
        float4 f1 = gp[1];
        float fs[8] = {f0.x, f0.y, f0.z, f0.w, f1.x, f1.y, f1.z, f1.w};
        __nv_bfloat162 hv[4], lv[4];
#pragma unroll
        for (int j = 0; j < 4; j++) {
            const float a = fs[2 * j], b = fs[2 * j + 1];
            const __nv_bfloat16 ha = __float2bfloat16_rn(a);
            const __nv_bfloat16 hb = __float2bfloat16_rn(b);
            hv[j].x = ha; hv[j].y = hb;
            lv[j].x = __float2bfloat16_rn(a - __bfloat162float(ha));
            lv[j].y = __float2bfloat16_rn(b - __bfloat162float(hb));
        }
        const uint32_t sw = SMEM_SWIZZLE_128B((uint32_t)(row * 128 + cc * 16));
        *reinterpret_cast<uint4*>(smem + off_hi + sw) =
            *reinterpret_cast<uint4*>(hv);
        *reinterpret_cast<uint4*>(smem + off_lo + sw) =
            *reinterpret_cast<uint4*>(lv);
    }
}

template <bool TSTORE>
__global__ void __launch_bounds__(256, 2)
gemm_mma(const float* __restrict__ A, const float* __restrict__ B,
         const float* __restrict__ bias, float* __restrict__ C,
         int M, int N, int K)
{
    extern __shared__ char smem[];
    const uint32_t sbase = smem_u32(smem);
    const int tid  = threadIdx.x;
    const int wid  = tid >> 5;
    const int lane = tid & 31;
    const int wm   = wid & 3;
    const int wn   = wid >> 2;
    const int bn   = blockIdx.x * 128;
    const int bm   = blockIdx.y * 128;

    const float* Ab = A + (size_t)bm * K;
    const float* Bb = B + (size_t)bn * K;

    uint32_t aAddr[2];
    {
        const int rlo = lane & 15;
        const int sub = (lane >> 4) * 16;
#pragma unroll
        for (int t = 0; t < 2; t++) {
            const int row = wm * 32 + t * 16 + rlo;
            aAddr[t] = sbase + SM_A_HI + row * 128
                     + (uint32_t)(sub ^ ((row & 7) << 4));
        }
    }
    uint32_t bAddr[4];
    {
        const int nlo = (lane & 7) + ((lane & 16) >> 1);
        const int sub = (lane & 8) << 1;
#pragma unroll
        for (int g = 0; g < 4; g++) {
            const int row = wn * 64 + g * 16 + nlo;
            bAddr[g] = sbase + SM_B_HI + row * 128
                     + (uint32_t)(sub ^ ((row & 7) << 4));
        }
    }

    float acc[2][8][4];
#pragma unroll
    for (int t = 0; t < 2; t++)
#pragma unroll
        for (int n = 0; n < 8; n++)
#pragma unroll
            for (int j = 0; j < 4; j++) acc[t][n][j] = 0.f;

    const int NC = K / G_BK;
    for (int c = 0; c < NC; c++) {
        load_split_tile(Ab, K, c * G_BK, smem, SM_A_HI, SM_A_LO, tid);
        load_split_tile(Bb, K, c * G_BK, smem, SM_B_HI, SM_B_LO, tid);
        __syncthreads();

#pragma unroll
        for (int ks = 0; ks < 4; ks++) {
            uint32_t a0 = aAddr[0], a1 = aAddr[1];
            uint32_t b0 = bAddr[0], b1 = bAddr[1], b2 = bAddr[2], b3 = bAddr[3];
            {
                const int subA = (lane >> 4) * 16;
                const int subB = (lane & 8) << 1;
                const int kso  = ks * 32;
#pragma unroll
                for (int t = 0; t < 2; t++) {
                    const int row = wm * 32 + t * 16 + (lane & 15);
                    const uint32_t mask = (row & 7) << 4;
                    const uint32_t adj = ((uint32_t)(subA + kso) ^ mask)
                                       - ((uint32_t)subA ^ mask);
                    if (t == 0) a0 += adj; else a1 += adj;
                }
                const int nlo = (lane & 7) + ((lane & 16) >> 1);
#pragma unroll
                for (int g = 0; g < 4; g++) {
                    const int row = wn * 64 + g * 16 + nlo;
                    const uint32_t mask = (row & 7) << 4;
                    const uint32_t adj = ((uint32_t)(subB + kso) ^ mask)
                                       - ((uint32_t)subB ^ mask);
                    if (g == 0) b0 += adj;
                    else if (g == 1) b1 += adj;
                    else if (g == 2) b2 += adj;
                    else b3 += adj;
                }
            }

            uint32_t Ah[2][4], Al[2][4];
            ldm_x4(Ah[0], a0);
            ldm_x4(Ah[1], a1);
            ldm_x4(Al[0], a0 + TILE_B);
            ldm_x4(Al[1], a1 + TILE_B);

            const uint32_t bA[4] = {b0, b1, b2, b3};
#pragma unroll
            for (int g = 0; g < 4; g++) {
                uint32_t Bh[4], Bl[4];
                ldm_x4(Bh, bA[g]);
                ldm_x4(Bl, bA[g] + TILE_B);
#pragma unroll
                for (int half = 0; half < 2; half++) {
                    const int n = g * 2 + half;
                    const uint32_t bh0 = Bh[half * 2], bh1 = Bh[half * 2 + 1];
                    const uint32_t bl0 = Bl[half * 2], bl1 = Bl[half * 2 + 1];
#pragma unroll
                    for (int t = 0; t < 2; t++) {
                        mma16816(acc[t][n], Ah[t], bh0, bh1);
                        mma16816(acc[t][n], Ah[t], bl0, bl1);
                        mma16816(acc[t][n], Al[t], bh0, bh1);
                    }
                }
            }
        }
        __syncthreads();
    }

    const int crow = bm + wm * 32 + (lane >> 2);
    const int ccol = bn + wn * 64 + (lane & 3) * 2;
#pragma unroll
    for (int t = 0; t < 2; t++) {
        const int r0 = crow + t * 16;
#pragma unroll
        for (int n = 0; n < 8; n++) {
            const int col = ccol + n * 8;
            if (TSTORE) {
                // C_T[col][row], row-stride MROWS
                C[(size_t)col * MROWS + r0]            = acc[t][n][0];
                C[(size_t)(col + 1) * MROWS + r0]      = acc[t][n][1];
                C[(size_t)col * MROWS + r0 + 8]        = acc[t][n][2];
                C[(size_t)(col + 1) * MROWS + r0 + 8]  = acc[t][n][3];
            } else {
                float bx = 0.f, by = 0.f;
                if (bias) { bx = __ldg(bias + col); by = __ldg(bias + col + 1); }
                *reinterpret_cast<float2*>(&C[(size_t)r0 * N + col]) =
                    make_float2(acc[t][n][0] + bx, acc[t][n][1] + by);
                *reinterpret_cast<float2*>(&C[(size_t)(r0 + 8) * N + col]) =
                    make_float2(acc[t][n][2] + bx, acc[t][n][3] + by);
            }
        }
    }
}

// ---------------------------------------------------------------------------
// Dim-major local 5x5 attention.
// qkvT layout: [1536 dims][16384 rows], row = b*4096 + y*64 + x.
//   q dims [0,512), k dims [512,1024), v dims [1024,1536); head h owns h*64..+63.
// One warp per (b, head, y, x-half); lane = pixel x = x0 + lane.
// Per head-dim j: coalesced row loads; dx-neighbors via __shfl, edge lanes via
// predicated direct loads. OOB neighbors contribute 0 to logits (zero-pad).
// Output: pixel-major g_att[row][512] via per-warp smem transpose.
// ---------------------------------------------------------------------------
#define ATT_STRIDE 66                       // floats per pixel row in smem
#define ATT_SMEM   (8 * 32 * ATT_STRIDE * 4)   // 67584 B per block

__global__ void __launch_bounds__(256)
local_attn_t(const float* __restrict__ qkvT, float* __restrict__ out)
{
    extern __shared__ float smf[];
    const int warpId = threadIdx.x >> 5;
    const int lane   = threadIdx.x & 31;
    const int W      = blockIdx.x * 8 + warpId;    // 0..4095

    const int x0   = (W & 1) * 32;
    const int y    = (W >> 1) & 63;
    const int head = (W >> 7) & 7;
    const int b    = W >> 10;
    const int x    = x0 + lane;
    const int r    = b * 4096 + y * 64 + x;
    const size_t R = (size_t)MROWS;

    const float* Qp = qkvT + (size_t)(head * 64) * R;
    const float* Kp = qkvT + (size_t)(512 + head * 64) * R + b * 4096;
    const float* Vp = qkvT + (size_t)(1024 + head * 64) * R + b * 4096;

    float dots[25];
#pragma unroll
    for (int f = 0; f < 25; f++) dots[f] = 0.f;

    // Phase 1: logits
#pragma unroll 2
    for (int j = 0; j < 64; j++) {
        const float q = Qp[(size_t)j * R + r];
        const float* kj = Kp + (size_t)j * R;
#pragma unroll
        for (int dy = 0; dy < 5; dy++) {
            const int yy = y + dy - 2;
            const bool yok = ((unsigned)yy < 64u);
            const float* krow = kj + yy * 64;
            const float kv = yok ? krow[x] : 0.f;
#pragma unroll
            for (int dx = 0; dx < 5; dx++) {
                const int sl = lane + dx - 2;
                float val = __shfl_sync(0xffffffffu, kv, sl & 31);
                if (sl < 0 || sl > 31) {
                    const int xx = x + dx - 2;
                    val = (yok && (unsigned)xx < 64u) ? krow[xx] : 0.f;
                }
                dots[dy * 5 + dx] += q * val;
            }
        }
    }

    // Softmax over 25 (per-lane, no cross-lane ops)
    float m = dots[0] * 0.125f;
#pragma unroll
    for (int f = 0; f < 25; f++) {
        dots[f] *= 0.125f;                    // 64^-0.5
        m = fmaxf(m, dots[f]);
    }
    float s = 0.f;
#pragma unroll
    for (int f = 0; f < 25; f++) { dots[f] = __expf(dots[f] - m); s += dots[f]; }
    const float inv = 1.0f / s;
#pragma unroll
    for (int f = 0; f < 25; f++) dots[f] *= inv;

    // Phase 2: weighted V, staged per-dim into smem
    float* so = smf + (warpId * 32 + lane) * ATT_STRIDE;
#pragma unroll 2
    for (int j = 0; j < 64; j++) {
        const float* vj = Vp + (size_t)j * R;
        float o = 0.f;
#pragma unroll
        for (int dy = 0; dy < 5; dy++) {
            const int yy = y + dy - 2;
            const bool yok = ((unsigned)yy < 64u);
            const float* vrow = vj + yy * 64;
            const float vv = yok ? vrow[x] : 0.f;
#pragma unroll
            for (int dx = 0; dx < 5; dx++) {
                const int sl = lane + dx - 2;
                float val = __shfl_sync(0xffffffffu, vv, sl & 31);
                if (sl < 0 || sl > 31) {
                    const int xx = x + dx - 2;
                    val = (yok && (unsigned)xx < 64u) ? vrow[xx] : 0.f;
                }
                o += dots[dy * 5 + dx] * val;
            }
        }
        so[j] = o;
    }
    __syncwarp();

    // Transpose-write to pixel-major out[r][head*64 + j]
    float* op = out + (size_t)r * INNER + head * 64;
#pragma unroll
    for (int jj = 0; jj < 64; jj += 4) {
        float2 a = *reinterpret_cast<const float2*>(so + jj);
        float2 c = *reinterpret_cast<const float2*>(so + jj + 2);
        *reinterpret_cast<float4*>(op + jj) = make_float4(a.x, a.y, c.x, c.y);
    }
}

// ---------------------------------------------------------------------------
// Launch
// ---------------------------------------------------------------------------
extern "C" void kernel_launch(void* const* d_in, const int* in_sizes, int n_in,
                              void* d_out, int out_size)
{
    const float* x     = (const float*)d_in[0];
    const float* w_qkv = (const float*)d_in[1];
    const float* w_out = (const float*)d_in[2];
    const float* b_out = (const float*)d_in[3];
    float* out = (float*)d_out;

    float* qkvT = nullptr;
    float* att  = nullptr;
    cudaGetSymbolAddress((void**)&qkvT, g_qkv);
    cudaGetSymbolAddress((void**)&att, g_att);

    cudaFuncSetAttribute(gemm_mma<true>,
                         cudaFuncAttributeMaxDynamicSharedMemorySize, SM_TOTAL);
    cudaFuncSetAttribute(gemm_mma<false>,
                         cudaFuncAttributeMaxDynamicSharedMemorySize, SM_TOTAL);
    cudaFuncSetAttribute(local_attn_t,
                         cudaFuncAttributeMaxDynamicSharedMemorySize, ATT_SMEM);

    // GEMM1: qkvT = (x @ w_qkv^T)^T, written dim-major [1536][16384]
    dim3 g1(QKV_N / 128, MROWS / 128);
    gemm_mma<true><<<g1, 256, SM_TOTAL>>>(x, w_qkv, nullptr, qkvT,
                                          MROWS, QKV_N, DIMM);

    // Local attention (dim-major in, pixel-major out)
    local_attn_t<<<512, 256, ATT_SMEM>>>(qkvT, att);

    // GEMM2: out = att @ w_out^T + b_out   [16384,512] x [512,512]^T
    dim3 g2(DIMM / 128, MROWS / 128);
    gemm_mma<false><<<g2, 256, SM_TOTAL>>>(att, w_out, b_out, out,
                                           MROWS, DIMM, INNER);
}

// round 9
// speedup vs baseline: 1.3502x; 1.3502x over previous
#include <cuda_runtime.h>
#include <cuda_bf16.h>
#include <cstdint>

// Problem constants (fixed by reference setup_inputs)
#define Bq     4
#define NPIX   4096          // 64*64
#define HEADS  8
#define HD     64
#define DIMM   512
#define INNER  512           // HEADS*HD
#define MROWS  (Bq*NPIX)     // 16384
#define QKV_N  (3*INNER)     // 1536

// Scratch (device globals — no runtime allocation allowed)
__device__ float g_qkv[(size_t)MROWS * QKV_N];   // ~100.7 MB (pixel-major)
__device__ float g_att[(size_t)MROWS * INNER];   // ~33.5 MB (pixel-major)

// ---------------------------------------------------------------------------
// Warp-level tensor-core primitives (base PTX — compile at compute_103)
// ---------------------------------------------------------------------------
__device__ __forceinline__ uint32_t smem_u32(const void* p) {
    uint32_t a;
    asm("{ .reg .u64 t; cvta.to.shared.u64 t, %1; cvt.u32.u64 %0, t; }"
        : "=r"(a) : "l"(p));
    return a;
}
__device__ __forceinline__ void ldm_x4(uint32_t* r, uint32_t addr) {
    asm volatile("ldmatrix.sync.aligned.m8n8.x4.shared.b16 {%0,%1,%2,%3}, [%4];"
                 : "=r"(r[0]), "=r"(r[1]), "=r"(r[2]), "=r"(r[3]) : "r"(addr));
}
__device__ __forceinline__ void mma16816(float* d, const uint32_t* a,
                                         uint32_t b0, uint32_t b1) {
    asm volatile(
        "mma.sync.aligned.m16n8k16.row.col.f32.bf16.bf16.f32 "
        "{%0,%1,%2,%3}, {%4,%5,%6,%7}, {%8,%9}, {%0,%1,%2,%3};"
        : "+f"(d[0]), "+f"(d[1]), "+f"(d[2]), "+f"(d[3])
        : "r"(a[0]), "r"(a[1]), "r"(a[2]), "r"(a[3]), "r"(b0), "r"(b1));
}
#define SMEM_SWIZZLE_128B(b) ((b) ^ (((b) >> 3) & 0x70))

// ---------------------------------------------------------------------------
// bf16-split GEMM via mma.sync: C[M,N] = A[M,K] @ B[N,K]^T (+ bias[N]).
// fp32 -> bf16 hi+lo; D = Ah*Bh + Ah*Bl + Al*Bh, fp32 accumulate.
// CTA 128x128, 256 threads (8 warps: 4 M x 2 N, warp tile 32x64), BK=64.
// (Proven R7 version, unchanged.)
// ---------------------------------------------------------------------------
#define G_BK     64
#define TILE_B   16384                      // one 128x64 bf16 tile
#define SM_A_HI  0
#define SM_A_LO  16384
#define SM_B_HI  32768
#define SM_B_LO  49152
#define SM_TOTAL 65536

__device__ __forceinline__ void load_split_tile(
    const float* __restrict__ src, int K, int k0,
    char* smem, int off_hi, int off_lo, int tid)
{
#pragma unroll
    for (int i = 0; i < 4; i++) {
        const int idx = tid + 256 * i;   // 0..1023 chunk id
        const int row = idx >> 3;
        const int cc  = idx & 7;
        const float4* gp = reinterpret_cast<const float4*>(
            src + (size_t)row * K + k0 + cc * 8);
        float4 f0 = gp[0];
        float4 f1 = gp[1];
        float fs[8] = {f0.x, f0.y, f0.z, f0.w, f1.x, f1.y, f1.z, f1.w};
        __nv_bfloat162 hv[4], lv[4];
#pragma unroll
        for (int j = 0; j < 4; j++) {
            const float a = fs[2 * j], b = fs[2 * j + 1];
            const __nv_bfloat16 ha = __float2bfloat16_rn(a);
            const __nv_bfloat16 hb = __float2bfloat16_rn(b);
            hv[j].x = ha; hv[j].y = hb;
            lv[j].x = __float2bfloat16_rn(a - __bfloat162float(ha));
            lv[j].y = __float2bfloat16_rn(b - __bfloat162float(hb));
        }
        const uint32_t sw = SMEM_SWIZZLE_128B((uint32_t)(row * 128 + cc * 16));
        *reinterpret_cast<uint4*>(smem + off_hi + sw) =
            *reinterpret_cast<uint4*>(hv);
        *reinterpret_cast<uint4*>(smem + off_lo + sw) =
            *reinterpret_cast<uint4*>(lv);
    }
}

__global__ void __launch_bounds__(256, 2)
gemm_mma(const float* __restrict__ A, const float* __restrict__ B,
         const float* __restrict__ bias, float* __restrict__ C,
         int M, int N, int K)
{
    extern __shared__ char smem[];
    const uint32_t sbase = smem_u32(smem);
    const int tid  = threadIdx.x;
    const int wid  = tid >> 5;
    const int lane = tid & 31;
    const int wm   = wid & 3;
    const int wn   = wid >> 2;
    const int bn   = blockIdx.x * 128;
    const int bm   = blockIdx.y * 128;

    const float* Ab = A + (size_t)bm * K;
    const float* Bb = B + (size_t)bn * K;

    uint32_t aAddr[2];
    {
        const int rlo = lane & 15;
        const int sub = (lane >> 4) * 16;
#pragma unroll
        for (int t = 0; t < 2; t++) {
            const int row = wm * 32 + t * 16 + rlo;
            aAddr[t] = sbase + SM_A_HI + row * 128
                     + (uint32_t)(sub ^ ((row & 7) << 4));
        }
    }
    uint32_t bAddr[4];
    {
        const int nlo = (lane & 7) + ((lane & 16) >> 1);
        const int sub = (lane & 8) << 1;
#pragma unroll
        for (int g = 0; g < 4; g++) {
            const int row = wn * 64 + g * 16 + nlo;
            bAddr[g] = sbase + SM_B_HI + row * 128
                     + (uint32_t)(sub ^ ((row & 7) << 4));
        }
    }

    float acc[2][8][4];
#pragma unroll
    for (int t = 0; t < 2; t++)
#pragma unroll
        for (int n = 0; n < 8; n++)
#pragma unroll
            for (int j = 0; j < 4; j++) acc[t][n][j] = 0.f;

    const int NC = K / G_BK;
    for (int c = 0; c < NC; c++) {
        load_split_tile(Ab, K, c * G_BK, smem, SM_A_HI, SM_A_LO, tid);
        load_split_tile(Bb, K, c * G_BK, smem, SM_B_HI, SM_B_LO, tid);
        __syncthreads();

#pragma unroll
        for (int ks = 0; ks < 4; ks++) {
            uint32_t a0 = aAddr[0], a1 = aAddr[1];
            uint32_t b0 = bAddr[0], b1 = bAddr[1], b2 = bAddr[2], b3 = bAddr[3];
            {
                const int subA = (lane >> 4) * 16;
                const int subB = (lane & 8) << 1;
                const int kso  = ks * 32;
#pragma unroll
                for (int t = 0; t < 2; t++) {
                    const int row = wm * 32 + t * 16 + (lane & 15);
                    const uint32_t mask = (row & 7) << 4;
                    const uint32_t adj = ((uint32_t)(subA + kso) ^ mask)
                                       - ((uint32_t)subA ^ mask);
                    if (t == 0) a0 += adj; else a1 += adj;
                }
                const int nlo = (lane & 7) + ((lane & 16) >> 1);
#pragma unroll
                for (int g = 0; g < 4; g++) {
                    const int row = wn * 64 + g * 16 + nlo;
                    const uint32_t mask = (row & 7) << 4;
                    const uint32_t adj = ((uint32_t)(subB + kso) ^ mask)
                                       - ((uint32_t)subB ^ mask);
                    if (g == 0) b0 += adj;
                    else if (g == 1) b1 += adj;
                    else if (g == 2) b2 += adj;
                    else b3 += adj;
                }
            }

            uint32_t Ah[2][4], Al[2][4];
            ldm_x4(Ah[0], a0);
            ldm_x4(Ah[1], a1);
            ldm_x4(Al[0], a0 + TILE_B);
            ldm_x4(Al[1], a1 + TILE_B);

            const uint32_t bA[4] = {b0, b1, b2, b3};
#pragma unroll
            for (int g = 0; g < 4; g++) {
                uint32_t Bh[4], Bl[4];
                ldm_x4(Bh, bA[g]);
                ldm_x4(Bl, bA[g] + TILE_B);
#pragma unroll
                for (int half = 0; half < 2; half++) {
                    const int n = g * 2 + half;
                    const uint32_t bh0 = Bh[half * 2], bh1 = Bh[half * 2 + 1];
                    const uint32_t bl0 = Bl[half * 2], bl1 = Bl[half * 2 + 1];
#pragma unroll
                    for (int t = 0; t < 2; t++) {
                        mma16816(acc[t][n], Ah[t], bh0, bh1);
                        mma16816(acc[t][n], Ah[t], bl0, bl1);
                        mma16816(acc[t][n], Al[t], bh0, bh1);
                    }
                }
            }
        }
        __syncthreads();
    }

    const int crow = bm + wm * 32 + (lane >> 2);
    const int ccol = bn + wn * 64 + (lane & 3) * 2;
#pragma unroll
    for (int t = 0; t < 2; t++) {
        const int r0 = crow + t * 16;
#pragma unroll
        for (int n = 0; n < 8; n++) {
            const int col = ccol + n * 8;
            float bx = 0.f, by = 0.f;
            if (bias) { bx = __ldg(bias + col); by = __ldg(bias + col + 1); }
            *reinterpret_cast<float2*>(&C[(size_t)r0 * N + col]) =
                make_float2(acc[t][n][0] + bx, acc[t][n][1] + by);
            *reinterpret_cast<float2*>(&C[(size_t)(r0 + 8) * N + col]) =
                make_float2(acc[t][n][2] + bx, acc[t][n][3] + by);
        }
    }
}

// ---------------------------------------------------------------------------
// Tiled local 5x5 attention, one head per block.
// Block = 256 threads = 16x16 pixel tile; grid = 16 tiles * 8 heads * 4 b.
// Smem stages the 20x20 halo of k (then v), 16 dims at a time, dim-major
// layout sm[16][20][21] so a warp's 25-neighbor reads are near-conflict-free.
// Thread = 1 pixel; q (16 dims/chunk) in registers; per dim 25 LDS + 25 FMA.
// OOB halo entries are zero -> logit contribution 0 (matches zero-padding).
// qkv row layout (pixel-major): q[0:512], k[512:1024], v[1024:1536].
// ---------------------------------------------------------------------------
#define CH 16            // dims per smem chunk

__global__ void __launch_bounds__(256)
local_attn_tile(const float* __restrict__ qkv, float* __restrict__ out)
{
    __shared__ float sm[CH][20][21];     // 26.9 KB

    const int tid  = threadIdx.x;
    const int px   = tid & 15;
    const int py   = tid >> 4;

    const int bid  = blockIdx.x;         // 0..511
    const int tx   = bid & 3;
    const int ty   = (bid >> 2) & 3;
    const int head = (bid >> 4) & 7;
    const int b    = bid >> 7;

    const int X = tx * 16 + px;
    const int Y = ty * 16 + py;
    const int r = b * 4096 + Y * 64 + X;

    const float* base  = qkv + (size_t)b * 4096 * QKV_N;
    const float* kbase = base + 512 + head * 64;    // + row*1536 + dim
    const float* vbase = base + 1024 + head * 64;
    const float* qrow  = qkv + (size_t)r * QKV_N + head * 64;

    float dots[25];
#pragma unroll
    for (int f = 0; f < 25; f++) dots[f] = 0.f;

    // ---- Phase 1: logits over 4 dim-chunks ----
    for (int jc = 0; jc < 4; jc++) {
        // load k halo chunk: 400 rows x 16 dims, 4 threads (float4) per row
        for (int s = tid; s < 1600; s += 256) {
            const int row = s >> 2;        // 0..399
            const int q4  = s & 3;
            const int hy  = row / 20, hx = row - hy * 20;
            const int gy  = ty * 16 + hy - 2;
            const int gx  = tx * 16 + hx - 2;
            float4 v = make_float4(0.f, 0.f, 0.f, 0.f);
            if ((unsigned)gy < 64u && (unsigned)gx < 64u)
                v = *reinterpret_cast<const float4*>(
                    kbase + (size_t)(gy * 64 + gx) * QKV_N + jc * CH + q4 * 4);
            sm[q4 * 4 + 0][hy][hx] = v.x;
            sm[q4 * 4 + 1][hy][hx] = v.y;
            sm[q4 * 4 + 2][hy][hx] = v.z;
            sm[q4 * 4 + 3][hy][hx] = v.w;
        }
        __syncthreads();

        float4 qv[4];
#pragma unroll
        for (int i = 0; i < 4; i++)
            qv[i] = reinterpret_cast<const float4*>(qrow + jc * CH)[i];
        const float qs[16] = {qv[0].x, qv[0].y, qv[0].z, qv[0].w,
                              qv[1].x, qv[1].y, qv[1].z, qv[1].w,
                              qv[2].x, qv[2].y, qv[2].z, qv[2].w,
                              qv[3].x, qv[3].y, qv[3].z, qv[3].w};
#pragma unroll
        for (int j = 0; j < CH; j++) {
            const float q = qs[j];
#pragma unroll
            for (int dy = 0; dy < 5; dy++) {
                const float* row = &sm[j][py + dy][px];
#pragma unroll
                for (int dx = 0; dx < 5; dx++)
                    dots[dy * 5 + dx] += q * row[dx];
            }
        }
        __syncthreads();
    }

    // ---- Softmax over 25 (per-thread) ----
    float m = -1e30f;
#pragma unroll
    for (int f = 0; f < 25; f++) {
        dots[f] *= 0.125f;                 // 64^-0.5
        m = fmaxf(m, dots[f]);
    }
    float s = 0.f;
#pragma unroll
    for (int f = 0; f < 25; f++) { dots[f] = __expf(dots[f] - m); s += dots[f]; }
    const float inv = 1.0f / s;
#pragma unroll
    for (int f = 0; f < 25; f++) dots[f] *= inv;

    // ---- Phase 2: weighted V over 4 dim-chunks ----
    float* op = out + (size_t)r * INNER + head * 64;
    for (int jc = 0; jc < 4; jc++) {
        for (int s = tid; s < 1600; s += 256) {
            const int row = s >> 2;
            const int q4  = s & 3;
            const int hy  = row / 20, hx = row - hy * 20;
            const int gy  = ty * 16 + hy - 2;
            const int gx  = tx * 16 + hx - 2;
            float4 v = make_float4(0.f, 0.f, 0.f, 0.f);
            if ((unsigned)gy < 64u && (unsigned)gx < 64u)
                v = *reinterpret_cast<const float4*>(
                    vbase + (size_t)(gy * 64 + gx) * QKV_N + jc * CH + q4 * 4);
            sm[q4 * 4 + 0][hy][hx] = v.x;
            sm[q4 * 4 + 1][hy][hx] = v.y;
            sm[q4 * 4 + 2][hy][hx] = v.z;
            sm[q4 * 4 + 3][hy][hx] = v.w;
        }
        __syncthreads();

        float o[16];
#pragma unroll
        for (int j = 0; j < CH; j++) {
            float acc = 0.f;
#pragma unroll
            for (int dy = 0; dy < 5; dy++) {
                const float* row = &sm[j][py + dy][px];
#pragma unroll
                for (int dx = 0; dx < 5; dx++)
                    acc += dots[dy * 5 + dx] * row[dx];
            }
            o[j] = acc;
        }
#pragma unroll
        for (int i = 0; i < 4; i++)
            *reinterpret_cast<float4*>(op + jc * CH + i * 4) =
                make_float4(o[4 * i], o[4 * i + 1], o[4 * i + 2], o[4 * i + 3]);
        __syncthreads();
    }
}

// ---------------------------------------------------------------------------
// Launch
// ---------------------------------------------------------------------------
extern "C" void kernel_launch(void* const* d_in, const int* in_sizes, int n_in,
                              void* d_out, int out_size)
{
    const float* x     = (const float*)d_in[0];
    const float* w_qkv = (const float*)d_in[1];
    const float* w_out = (const float*)d_in[2];
    const float* b_out = (const float*)d_in[3];
    float* out = (float*)d_out;

    float* qkv = nullptr;
    float* att = nullptr;
    cudaGetSymbolAddress((void**)&qkv, g_qkv);
    cudaGetSymbolAddress((void**)&att, g_att);

    cudaFuncSetAttribute(gemm_mma,
                         cudaFuncAttributeMaxDynamicSharedMemorySize, SM_TOTAL);

    // GEMM1: qkv = x @ w_qkv^T   [16384,512] x [1536,512]^T -> [16384,1536]
    dim3 g1(QKV_N / 128, MROWS / 128);
    gemm_mma<<<g1, 256, SM_TOTAL>>>(x, w_qkv, nullptr, qkv, MROWS, QKV_N, DIMM);

    // Local attention (tiled, per-head) -> [16384, 512]
    local_attn_tile<<<512, 256>>>(qkv, att);

    // GEMM2: out = att @ w_out^T + b_out   [16384,512] x [512,512]^T
    dim3 g2(DIMM / 128, MROWS / 128);
    gemm_mma<<<g2, 256, SM_TOTAL>>>(att, w_out, b_out, out, MROWS, DIMM, INNER);
}

// round 10
// speedup vs baseline: 1.5543x; 1.1512x over previous
#include <cuda_runtime.h>
#include <cuda_bf16.h>
#include <cstdint>

// Problem constants (fixed by reference setup_inputs)
#define Bq     4
#define NPIX   4096          // 64*64
#define HEADS  8
#define HD     64
#define DIMM   512
#define INNER  512           // HEADS*HD
#define MROWS  (Bq*NPIX)     // 16384
#define QKV_N  (3*INNER)     // 1536

// Scratch (device globals — no runtime allocation allowed)
__device__ float         g_qkv[(size_t)MROWS * QKV_N];   // fp32 qkv (GEMM1 out)
__device__ __nv_bfloat16 g_xh[(size_t)MROWS * DIMM];     // x hi/lo
__device__ __nv_bfloat16 g_xl[(size_t)MROWS * DIMM];
__device__ __nv_bfloat16 g_wqh[(size_t)QKV_N * DIMM];    // w_qkv hi/lo
__device__ __nv_bfloat16 g_wql[(size_t)QKV_N * DIMM];
__device__ __nv_bfloat16 g_woh[(size_t)DIMM * INNER];    // w_out hi/lo
__device__ __nv_bfloat16 g_wol[(size_t)DIMM * INNER];
__device__ __nv_bfloat16 g_ah[(size_t)MROWS * INNER];    // att hi/lo
__device__ __nv_bfloat16 g_al[(size_t)MROWS * INNER];

// ---------------------------------------------------------------------------
// Primitives (base PTX only — must compile at compute_103)
// ---------------------------------------------------------------------------
__device__ __forceinline__ uint32_t smem_u32(const void* p) {
    uint32_t a;
    asm("{ .reg .u64 t; cvta.to.shared.u64 t, %1; cvt.u32.u64 %0, t; }"
        : "=r"(a) : "l"(p));
    return a;
}
__device__ __forceinline__ void ldm_x4(uint32_t* r, uint32_t addr) {
    asm volatile("ldmatrix.sync.aligned.m8n8.x4.shared.b16 {%0,%1,%2,%3}, [%4];"
                 : "=r"(r[0]), "=r"(r[1]), "=r"(r[2]), "=r"(r[3]) : "r"(addr));
}
__device__ __forceinline__ void mma16816(float* d, const uint32_t* a,
                                         uint32_t b0, uint32_t b1) {
    asm volatile(
        "mma.sync.aligned.m16n8k16.row.col.f32.bf16.bf16.f32 "
        "{%0,%1,%2,%3}, {%4,%5,%6,%7}, {%8,%9}, {%0,%1,%2,%3};"
        : "+f"(d[0]), "+f"(d[1]), "+f"(d[2]), "+f"(d[3])
        : "r"(a[0]), "r"(a[1]), "r"(a[2]), "r"(a[3]), "r"(b0), "r"(b1));
}
__device__ __forceinline__ void cp_async16(uint32_t dst, const void* src) {
    asm volatile("cp.async.cg.shared.global [%0], [%1], 16;"
                 :: "r"(dst), "l"(src));
}
#define CP_COMMIT() asm volatile("cp.async.commit_group;" ::: "memory")
#define CP_WAIT1()  asm volatile("cp.async.wait_group 1;" ::: "memory")
#define CP_WAIT0()  asm volatile("cp.async.wait_group 0;" ::: "memory")

// ---------------------------------------------------------------------------
// fp32 -> bf16 hi/lo split (elementwise)
// ---------------------------------------------------------------------------
__global__ void __launch_bounds__(256)
split_bf16(const float* __restrict__ in, __nv_bfloat16* __restrict__ hi,
           __nv_bfloat16* __restrict__ lo, int n4)
{
    const int i = blockIdx.x * 256 + threadIdx.x;
    if (i >= n4) return;
    float4 f = reinterpret_cast<const float4*>(in)[i];
    __nv_bfloat162 h[2], l[2];
    const float fs[4] = {f.x, f.y, f.z, f.w};
#pragma unroll
    for (int j = 0; j < 2; j++) {
        const float a = fs[2 * j], b = fs[2 * j + 1];
        const __nv_bfloat16 ha = __float2bfloat16_rn(a);
        const __nv_bfloat16 hb = __float2bfloat16_rn(b);
        h[j].x = ha; h[j].y = hb;
        l[j].x = __float2bfloat16_rn(a - __bfloat162float(ha));
        l[j].y = __float2bfloat16_rn(b - __bfloat162float(hb));
    }
    reinterpret_cast<uint2*>(hi)[i] = *reinterpret_cast<uint2*>(h);
    reinterpret_cast<uint2*>(lo)[i] = *reinterpret_cast<uint2*>(l);
}

// ---------------------------------------------------------------------------
// bf16-split GEMM, pre-converted operands, cp.async double-buffered.
// C[M,N] = A[M,512] @ B[N,512]^T (+bias), A/B given as bf16 hi+lo pairs.
// D = Ah*Bh + Ah*Bl + Al*Bh (fp32 acc). CTA 128x128, 256 thr, BK=64, NC=8.
// Stage layout (64KB): A_HI 0 | A_LO 16K | B_HI 32K | B_LO 48K. 2 stages.
// ---------------------------------------------------------------------------
#define TILE_B   16384
#define ST_SZ    65536
#define GSMEM    (2 * ST_SZ)

__global__ void __launch_bounds__(256)
gemm_bf16(const __nv_bfloat16* __restrict__ Ah,
          const __nv_bfloat16* __restrict__ Al,
          const __nv_bfloat16* __restrict__ Bh,
          const __nv_bfloat16* __restrict__ Bl,
          const float* __restrict__ bias, float* __restrict__ C, int N)
{
    extern __shared__ char smem[];
    const uint32_t sbase = smem_u32(smem);
    const int tid  = threadIdx.x;
    const int wid  = tid >> 5;
    const int lane = tid & 31;
    const int wm   = wid & 3;
    const int wn   = wid >> 2;
    const int bn   = blockIdx.x * 128;
    const int bm   = blockIdx.y * 128;

    // cp.async one 4-tile chunk (k0..k0+63) into stage
    auto cp_chunk = [&](int stage, int k0) {
        const uint32_t sb = sbase + stage * ST_SZ;
#pragma unroll
        for (int i = 0; i < 4; i++) {
            const int idx = tid + 256 * i;           // 0..1023
            const int row = idx >> 3;
            const int g   = idx & 7;
            const uint32_t off =
                (uint32_t)((row * 128 + g * 16) ^ ((row & 7) << 4));
            const size_t ao = (size_t)(bm + row) * 512 + k0 + g * 8;
            const size_t bo = (size_t)(bn + row) * 512 + k0 + g * 8;
            cp_async16(sb + off,         Ah + ao);
            cp_async16(sb + 16384 + off, Al + ao);
            cp_async16(sb + 32768 + off, Bh + bo);
            cp_async16(sb + 49152 + off, Bl + bo);
        }
    };

    // ldmatrix base addresses (stage 0)
    uint32_t aAddr[2];
    {
        const int rlo = lane & 15;
        const int sub = (lane >> 4) * 16;
#pragma unroll
        for (int t = 0; t < 2; t++) {
            const int row = wm * 32 + t * 16 + rlo;
            aAddr[t] = sbase + row * 128 + (uint32_t)(sub ^ ((row & 7) << 4));
        }
    }
    uint32_t bAddr[4];
    {
        const int nlo = (lane & 7) + ((lane & 16) >> 1);
        const int sub = (lane & 8) << 1;
#pragma unroll
        for (int g = 0; g < 4; g++) {
            const int row = wn * 64 + g * 16 + nlo;
            bAddr[g] = sbase + 32768 + row * 128
                     + (uint32_t)(sub ^ ((row & 7) << 4));
        }
    }

    float acc[2][8][4];
#pragma unroll
    for (int t = 0; t < 2; t++)
#pragma unroll
        for (int n = 0; n < 8; n++)
#pragma unroll
            for (int j = 0; j < 4; j++) acc[t][n][j] = 0.f;

    // prologue: fill both stages
    cp_chunk(0, 0);
    CP_COMMIT();
    cp_chunk(1, 64);
    CP_COMMIT();

    const int NC = 8;   // K = 512
    for (int c = 0; c < NC; c++) {
        if (c == NC - 1) { CP_WAIT0(); } else { CP_WAIT1(); }
        __syncthreads();

        const uint32_t so = (uint32_t)((c & 1) * ST_SZ);
#pragma unroll
        for (int ks = 0; ks < 4; ks++) {
            uint32_t a0 = aAddr[0] + so, a1 = aAddr[1] + so;
            uint32_t bA[4];
#pragma unroll
            for (int g = 0; g < 4; g++) bA[g] = bAddr[g] + so;
            {
                const int subA = (lane >> 4) * 16;
                const int subB = (lane & 8) << 1;
                const int kso  = ks * 32;
#pragma unroll
                for (int t = 0; t < 2; t++) {
                    const int row = wm * 32 + t * 16 + (lane & 15);
                    const uint32_t mask = (row & 7) << 4;
                    const uint32_t adj = ((uint32_t)(subA + kso) ^ mask)
                                       - ((uint32_t)subA ^ mask);
                    if (t == 0) a0 += adj; else a1 += adj;
                }
                const int nlo = (lane & 7) + ((lane & 16) >> 1);
#pragma unroll
                for (int g = 0; g < 4; g++) {
                    const int row = wn * 64 + g * 16 + nlo;
                    const uint32_t mask = (row & 7) << 4;
                    bA[g] += ((uint32_t)(subB + kso) ^ mask)
                           - ((uint32_t)subB ^ mask);
                }
            }

            uint32_t Ahf[2][4], Alf[2][4];
            ldm_x4(Ahf[0], a0);
            ldm_x4(Ahf[1], a1);
            ldm_x4(Alf[0], a0 + TILE_B);
            ldm_x4(Alf[1], a1 + TILE_B);
            uint32_t Bhf[4][4], Blf[4][4];
#pragma unroll
            for (int g = 0; g < 4; g++) {
                ldm_x4(Bhf[g], bA[g]);
                ldm_x4(Blf[g], bA[g] + TILE_B);
            }

            // pass-major order: same-acc reuse distance = 16 MMAs
#pragma unroll
            for (int g = 0; g < 4; g++)
#pragma unroll
                for (int h = 0; h < 2; h++)
#pragma unroll
                    for (int t = 0; t < 2; t++)
                        mma16816(acc[t][g * 2 + h], Ahf[t],
                                 Bhf[g][h * 2], Bhf[g][h * 2 + 1]);
#pragma unroll
            for (int g = 0; g < 4; g++)
#pragma unroll
                for (int h = 0; h < 2; h++)
#pragma unroll
                    for (int t = 0; t < 2; t++)
                        mma16816(acc[t][g * 2 + h], Ahf[t],
                                 Blf[g][h * 2], Blf[g][h * 2 + 1]);
#pragma unroll
            for (int g = 0; g < 4; g++)
#pragma unroll
                for (int h = 0; h < 2; h++)
#pragma unroll
                    for (int t = 0; t < 2; t++)
                        mma16816(acc[t][g * 2 + h], Alf[t],
                                 Bhf[g][h * 2], Bhf[g][h * 2 + 1]);
        }
        __syncthreads();

        if (c + 2 < NC) {
            cp_chunk(c & 1, (c + 2) * 64);
            CP_COMMIT();
        }
    }

    const int crow = bm + wm * 32 + (lane >> 2);
    const int ccol = bn + wn * 64 + (lane & 3) * 2;
#pragma unroll
    for (int t = 0; t < 2; t++) {
        const int r0 = crow + t * 16;
#pragma unroll
        for (int n = 0; n < 8; n++) {
            const int col = ccol + n * 8;
            float bx = 0.f, by = 0.f;
            if (bias) { bx = __ldg(bias + col); by = __ldg(bias + col + 1); }
            *reinterpret_cast<float2*>(&C[(size_t)r0 * N + col]) =
                make_float2(acc[t][n][0] + bx, acc[t][n][1] + by);
            *reinterpret_cast<float2*>(&C[(size_t)(r0 + 8) * N + col]) =
                make_float2(acc[t][n][2] + bx, acc[t][n][3] + by);
        }
    }
}

// ---------------------------------------------------------------------------
// Tiled local 5x5 attention, one head per block, CH=32 dims per stage.
// Block = 256 threads = 16x16 pixel tile. Smem: dim-pair layout
// sm[16 pairs][20][21][2] -> conflict-free LDS.64 neighbor reads.
// Output written as bf16 hi/lo split (feeds GEMM2 directly).
// OOB halo entries zero -> logit contribution 0 (matches zero-padding).
// ---------------------------------------------------------------------------
#define ATT_SMEM (16 * 20 * 21 * 2 * 4)   // 53760 B
#define SIDX(p, hy, hx) ((((p) * 20 + (hy)) * 21 + (hx)) * 2)

__global__ void __launch_bounds__(256)
local_attn_tile(const float* __restrict__ qkv,
                __nv_bfloat16* __restrict__ oh,
                __nv_bfloat16* __restrict__ ol)
{
    extern __shared__ float smf[];

    const int tid  = threadIdx.x;
    const int px   = tid & 15;
    const int py   = tid >> 4;

    const int bid  = blockIdx.x;         // 0..511
    const int tx   = bid & 3;
    const int ty   = (bid >> 2) & 3;
    const int head = (bid >> 4) & 7;
    const int b    = bid >> 7;

    const int X = tx * 16 + px;
    const int Y = ty * 16 + py;
    const int r = b * 4096 + Y * 64 + X;

    const float* base  = qkv + (size_t)b * 4096 * QKV_N;
    const float* kbase = base + 512 + head * 64;
    const float* vbase = base + 1024 + head * 64;
    const float* qrow  = qkv + (size_t)r * QKV_N + head * 64;

    float dots[25];
#pragma unroll
    for (int f = 0; f < 25; f++) dots[f] = 0.f;

    // ---- Phase 1: logits, 2 chunks of 32 dims ----
    for (int jc = 0; jc < 2; jc++) {
        for (int s = tid; s < 3200; s += 256) {      // 400 rows x 8 granules
            const int row = s >> 3;
            const int q4  = s & 7;
            const int hy  = row / 20, hx = row - hy * 20;
            const int gy  = ty * 16 + hy - 2;
            const int gx  = tx * 16 + hx - 2;
            float4 v = make_float4(0.f, 0.f, 0.f, 0.f);
            if ((unsigned)gy < 64u && (unsigned)gx < 64u)
                v = *reinterpret_cast<const float4*>(
                    kbase + (size_t)(gy * 64 + gx) * QKV_N + jc * 32 + q4 * 4);
            *reinterpret_cast<float2*>(&smf[SIDX(2 * q4, hy, hx)]) =
                make_float2(v.x, v.y);
            *reinterpret_cast<float2*>(&smf[SIDX(2 * q4 + 1, hy, hx)]) =
                make_float2(v.z, v.w);
        }
        __syncthreads();

        float qs[32];
#pragma unroll
        for (int i = 0; i < 8; i++) {
            float4 qv = reinterpret_cast<const float4*>(qrow + jc * 32)[i];
            qs[4 * i] = qv.x; qs[4 * i + 1] = qv.y;
            qs[4 * i + 2] = qv.z; qs[4 * i + 3] = qv.w;
        }
#pragma unroll
        for (int p = 0; p < 16; p++) {
            const float q0 = qs[2 * p], q1 = qs[2 * p + 1];
#pragma unroll
            for (int dy = 0; dy < 5; dy++) {
#pragma unroll
                for (int dx = 0; dx < 5; dx++) {
                    const float2 kv = *reinterpret_cast<const float2*>(
                        &smf[SIDX(p, py + dy, px + dx)]);
                    dots[dy * 5 + dx] += q0 * kv.x + q1 * kv.y;
                }
            }
        }
        __syncthreads();
    }

    // ---- Softmax over 25 (per-thread) ----
    float m = -1e30f;
#pragma unroll
    for (int f = 0; f < 25; f++) {
        dots[f] *= 0.125f;                 // 64^-0.5
        m = fmaxf(m, dots[f]);
    }
    float s = 0.f;
#pragma unroll
    for (int f = 0; f < 25; f++) { dots[f] = __expf(dots[f] - m); s += dots[f]; }
    const float inv = 1.0f / s;
#pragma unroll
    for (int f = 0; f < 25; f++) dots[f] *= inv;

    // ---- Phase 2: weighted V, split-write bf16 hi/lo ----
    for (int jc = 0; jc < 2; jc++) {
        for (int s = tid; s < 3200; s += 256) {
            const int row = s >> 3;
            const int q4  = s & 7;
            const int hy  = row / 20, hx = row - hy * 20;
            const int gy  = ty * 16 + hy - 2;
            const int gx  = tx * 16 + hx - 2;
            float4 v = make_float4(0.f, 0.f, 0.f, 0.f);
            if ((unsigned)gy < 64u && (unsigned)gx < 64u)
                v = *reinterpret_cast<const float4*>(
                    vbase + (size_t)(gy * 64 + gx) * QKV_N + jc * 32 + q4 * 4);
            *reinterpret_cast<float2*>(&smf[SIDX(2 * q4, hy, hx)]) =
                make_float2(v.x, v.y);
            *reinterpret_cast<float2*>(&smf[SIDX(2 * q4 + 1, hy, hx)]) =
                make_float2(v.z, v.w);
        }
        __syncthreads();

        float o[32];
#pragma unroll
        for (int p = 0; p < 16; p++) {
            float o0 = 0.f, o1 = 0.f;
#pragma unroll
            for (int dy = 0; dy < 5; dy++) {
#pragma unroll
                for (int dx = 0; dx < 5; dx++) {
                    const float2 vv = *reinterpret_cast<const float2*>(
                        &smf[SIDX(p, py + dy, px + dx)]);
                    const float w = dots[dy * 5 + dx];
                    o0 += w * vv.x;
                    o1 += w * vv.y;
                }
            }
            o[2 * p] = o0;
            o[2 * p + 1] = o1;
        }

        __nv_bfloat162 hb[16], lb[16];
#pragma unroll
        for (int i = 0; i < 16; i++) {
            const float a = o[2 * i], c = o[2 * i + 1];
            const __nv_bfloat16 ha = __float2bfloat16_rn(a);
            const __nv_bfloat16 hc = __float2bfloat16_rn(c);
            hb[i].x = ha; hb[i].y = hc;
            lb[i].x = __float2bfloat16_rn(a - __bfloat162float(ha));
            lb[i].y = __float2bfloat16_rn(c - __bfloat162float(hc));
        }
        const size_t oo = (size_t)r * INNER + head * 64 + jc * 32;
        reinterpret_cast<uint4*>(oh + oo)[0] = reinterpret_cast<uint4*>(hb)[0];
        reinterpret_cast<uint4*>(oh + oo)[1] = reinterpret_cast<uint4*>(hb)[1];
        reinterpret_cast<uint4*>(oh + oo)[2] = reinterpret_cast<uint4*>(hb)[2];
        reinterpret_cast<uint4*>(oh + oo)[3] = reinterpret_cast<uint4*>(hb)[3];
        reinterpret_cast<uint4*>(ol + oo)[0] = reinterpret_cast<uint4*>(lb)[0];
        reinterpret_cast<uint4*>(ol + oo)[1] = reinterpret_cast<uint4*>(lb)[1];
        reinterpret_cast<uint4*>(ol + oo)[2] = reinterpret_cast<uint4*>(lb)[2];
        reinterpret_cast<uint4*>(ol + oo)[3] = reinterpret_cast<uint4*>(lb)[3];
        __syncthreads();
    }
}

// ---------------------------------------------------------------------------
// Launch
// ---------------------------------------------------------------------------
extern "C" void kernel_launch(void* const* d_in, const int* in_sizes, int n_in,
                              void* d_out, int out_size)
{
    const float* x     = (const float*)d_in[0];
    const float* w_qkv = (const float*)d_in[1];
    const float* w_out = (const float*)d_in[2];
    const float* b_out = (const float*)d_in[3];
    float* out = (float*)d_out;

    float *qkv;
    __nv_bfloat16 *xh, *xl, *wqh, *wql, *woh, *wol, *ah, *al;
    cudaGetSymbolAddress((void**)&qkv, g_qkv);
    cudaGetSymbolAddress((void**)&xh,  g_xh);
    cudaGetSymbolAddress((void**)&xl,  g_xl);
    cudaGetSymbolAddress((void**)&wqh, g_wqh);
    cudaGetSymbolAddress((void**)&wql, g_wql);
    cudaGetSymbolAddress((void**)&woh, g_woh);
    cudaGetSymbolAddress((void**)&wol, g_wol);
    cudaGetSymbolAddress((void**)&ah,  g_ah);
    cudaGetSymbolAddress((void**)&al,  g_al);

    cudaFuncSetAttribute(gemm_bf16,
                         cudaFuncAttributeMaxDynamicSharedMemorySize, GSMEM);
    cudaFuncSetAttribute(local_attn_tile,
                         cudaFuncAttributeMaxDynamicSharedMemorySize, ATT_SMEM);

    // Pre-split inputs to bf16 hi/lo
    split_bf16<<<(MROWS * DIMM / 4 + 255) / 256, 256>>>(x, xh, xl,
                                                        MROWS * DIMM / 4);
    split_bf16<<<(QKV_N * DIMM / 4 + 255) / 256, 256>>>(w_qkv, wqh, wql,
                                                        QKV_N * DIMM / 4);
    split_bf16<<<(DIMM * INNER / 4 + 255) / 256, 256>>>(w_out, woh, wol,
                                                        DIMM * INNER / 4);

    // GEMM1: qkv = x @ w_qkv^T   -> fp32 [16384,1536]
    dim3 g1(QKV_N / 128, MROWS / 128);
    gemm_bf16<<<g1, 256, GSMEM>>>(xh, xl, wqh, wql, nullptr, qkv, QKV_N);

    // Local attention -> bf16 hi/lo [16384,512]
    local_attn_tile<<<512, 256, ATT_SMEM>>>(qkv, ah, al);

    // GEMM2: out = att @ w_out^T + b_out -> fp32 [16384,512]
    dim3 g2(DIMM / 128, MROWS / 128);
    gemm_bf16<<<g2, 256, GSMEM>>>(ah, al, woh, wol, b_out, out, DIMM);
}

// round 13
// speedup vs baseline: 1.6666x; 1.0722x over previous
#include <cuda_runtime.h>
#include <cuda_bf16.h>
#include <cstdint>

// Problem constants (fixed by reference setup_inputs)
#define Bq     4
#define NPIX   4096          // 64*64
#define HEADS  8
#define HD     64
#define DIMM   512
#define INNER  512           // HEADS*HD
#define MROWS  (Bq*NPIX)     // 16384
#define QKV_N  (3*INNER)     // 1536

// Scratch (device globals — no runtime allocation allowed)
__device__ float         g_qkv[(size_t)MROWS * QKV_N];   // fp32 qkv (GEMM1 out)
__device__ __nv_bfloat16 g_xh[(size_t)MROWS * DIMM];     // x hi/lo
__device__ __nv_bfloat16 g_xl[(size_t)MROWS * DIMM];
__device__ __nv_bfloat16 g_wqh[(size_t)QKV_N * DIMM];    // w_qkv hi/lo
__device__ __nv_bfloat16 g_wql[(size_t)QKV_N * DIMM];
__device__ __nv_bfloat16 g_woh[(size_t)DIMM * INNER];    // w_out hi/lo
__device__ __nv_bfloat16 g_wol[(size_t)DIMM * INNER];
__device__ __nv_bfloat16 g_ah[(size_t)MROWS * INNER];    // att hi/lo
__device__ __nv_bfloat16 g_al[(size_t)MROWS * INNER];

// ---------------------------------------------------------------------------
// Primitives (base PTX only — must compile at compute_103)
// ---------------------------------------------------------------------------
__device__ __forceinline__ uint32_t smem_u32(const void* p) {
    uint32_t a;
    asm("{ .reg .u64 t; cvta.to.shared.u64 t, %1; cvt.u32.u64 %0, t; }"
        : "=r"(a) : "l"(p));
    return a;
}
__device__ __forceinline__ void ldm_x4(uint32_t* r, uint32_t addr) {
    asm volatile("ldmatrix.sync.aligned.m8n8.x4.shared.b16 {%0,%1,%2,%3}, [%4];"
                 : "=r"(r[0]), "=r"(r[1]), "=r"(r[2]), "=r"(r[3]) : "r"(addr));
}
__device__ __forceinline__ void mma16816(float* d, const uint32_t* a,
                                         uint32_t b0, uint32_t b1) {
    asm volatile(
        "mma.sync.aligned.m16n8k16.row.col.f32.bf16.bf16.f32 "
        "{%0,%1,%2,%3}, {%4,%5,%6,%7}, {%8,%9}, {%0,%1,%2,%3};"
        : "+f"(d[0]), "+f"(d[1]), "+f"(d[2]), "+f"(d[3])
        : "r"(a[0]), "r"(a[1]), "r"(a[2]), "r"(a[3]), "r"(b0), "r"(b1));
}
__device__ __forceinline__ void cp_async16(uint32_t dst, const void* src) {
    asm volatile("cp.async.cg.shared.global [%0], [%1], 16;"
                 :: "r"(dst), "l"(src));
}
#define CP_COMMIT() asm volatile("cp.async.commit_group;" ::: "memory")
#define CP_WAIT0()  asm volatile("cp.async.wait_group 0;" ::: "memory")

// ---------------------------------------------------------------------------
// fp32 -> bf16 hi/lo split (elementwise)
// ---------------------------------------------------------------------------
__global__ void __launch_bounds__(256)
split_bf16(const float* __restrict__ in, __nv_bfloat16* __restrict__ hi,
           __nv_bfloat16* __restrict__ lo, int n4)
{
    const int i = blockIdx.x * 256 + threadIdx.x;
    if (i >= n4) return;
    float4 f = reinterpret_cast<const float4*>(in)[i];
    __nv_bfloat162 h[2], l[2];
    const float fs[4] = {f.x, f.y, f.z, f.w};
#pragma unroll
    for (int j = 0; j < 2; j++) {
        const float a = fs[2 * j], b = fs[2 * j + 1];
        const __nv_bfloat16 ha = __float2bfloat16_rn(a);
        const __nv_bfloat16 hb = __float2bfloat16_rn(b);
        h[j].x = ha; h[j].y = hb;
        l[j].x = __float2bfloat16_rn(a - __bfloat162float(ha));
        l[j].y = __float2bfloat16_rn(b - __bfloat162float(hb));
    }
    reinterpret_cast<uint2*>(hi)[i] = *reinterpret_cast<uint2*>(h);
    reinterpret_cast<uint2*>(lo)[i] = *reinterpret_cast<uint2*>(l);
}

// ---------------------------------------------------------------------------
// bf16-split GEMM, pre-converted operands. Single 64KB stage, 2 CTAs/SM —
// inter-CTA overlap hides the exposed cp.async phase.
// C[M,N] = A[M,512] @ B[N,512]^T (+bias); D = Ah*Bh + Al*Bh + Ah*Bl.
// CTA 128x128, 256 thr, BK=64, 8 chunks.
// Stage layout: A_HI 0 | A_LO 16K | B_HI 32K | B_LO 48K.
// ---------------------------------------------------------------------------
#define TILE_B   16384
#define GSMEM    65536

__global__ void __launch_bounds__(256, 2)
gemm_bf16(const __nv_bfloat16* __restrict__ Ah,
          const __nv_bfloat16* __restrict__ Al,
          const __nv_bfloat16* __restrict__ Bh,
          const __nv_bfloat16* __restrict__ Bl,
          const float* __restrict__ bias, float* __restrict__ C, int N)
{
    extern __shared__ char smem[];
    const uint32_t sbase = smem_u32(smem);
    const int tid  = threadIdx.x;
    const int wid  = tid >> 5;
    const int lane = tid & 31;
    const int wm   = wid & 3;
    const int wn   = wid >> 2;
    const int bn   = blockIdx.x * 128;
    const int bm   = blockIdx.y * 128;

    // ldmatrix base addresses
    uint32_t aAddr[2];
    {
        const int rlo = lane & 15;
        const int sub = (lane >> 4) * 16;
#pragma unroll
        for (int t = 0; t < 2; t++) {
            const int row = wm * 32 + t * 16 + rlo;
            aAddr[t] = sbase + row * 128 + (uint32_t)(sub ^ ((row & 7) << 4));
        }
    }
    uint32_t bAddr[4];
    {
        const int nlo = (lane & 7) + ((lane & 16) >> 1);
        const int sub = (lane & 8) << 1;
#pragma unroll
        for (int g = 0; g < 4; g++) {
            const int row = wn * 64 + g * 16 + nlo;
            bAddr[g] = sbase + 32768 + row * 128
                     + (uint32_t)(sub ^ ((row & 7) << 4));
        }
    }

    float acc[2][8][4];
#pragma unroll
    for (int t = 0; t < 2; t++)
#pragma unroll
        for (int n = 0; n < 8; n++)
#pragma unroll
            for (int j = 0; j < 4; j++) acc[t][n][j] = 0.f;

    for (int c = 0; c < 8; c++) {
        // stage chunk c (k0 = c*64)
        {
            const int k0 = c * 64;
#pragma unroll
            for (int i = 0; i < 4; i++) {
                const int idx = tid + 256 * i;           // 0..1023
                const int row = idx >> 3;
                const int g   = idx & 7;
                const uint32_t off =
                    (uint32_t)((row * 128 + g * 16) ^ ((row & 7) << 4));
                const size_t ao = (size_t)(bm + row) * 512 + k0 + g * 8;
                const size_t bo = (size_t)(bn + row) * 512 + k0 + g * 8;
                cp_async16(sbase + off,         Ah + ao);
                cp_async16(sbase + 16384 + off, Al + ao);
                cp_async16(sbase + 32768 + off, Bh + bo);
                cp_async16(sbase + 49152 + off, Bl + bo);
            }
        }
        CP_COMMIT();
        CP_WAIT0();
        __syncthreads();

#pragma unroll
        for (int ks = 0; ks < 4; ks++) {
            uint32_t a0 = aAddr[0], a1 = aAddr[1];
            uint32_t bA[4];
#pragma unroll
            for (int g = 0; g < 4; g++) bA[g] = bAddr[g];
            {
                const int subA = (lane >> 4) * 16;
                const int subB = (lane & 8) << 1;
                const int kso  = ks * 32;
#pragma unroll
                for (int t = 0; t < 2; t++) {
                    const int row = wm * 32 + t * 16 + (lane & 15);
                    const uint32_t mask = (row & 7) << 4;
                    const uint32_t adj = ((uint32_t)(subA + kso) ^ mask)
                                       - ((uint32_t)subA ^ mask);
                    if (t == 0) a0 += adj; else a1 += adj;
                }
                const int nlo = (lane & 7) + ((lane & 16) >> 1);
#pragma unroll
                for (int g = 0; g < 4; g++) {
                    const int row = wn * 64 + g * 16 + nlo;
                    const uint32_t mask = (row & 7) << 4;
                    bA[g] += ((uint32_t)(subB + kso) ^ mask)
                           - ((uint32_t)subB ^ mask);
                }
            }

            uint32_t Ahf[2][4], Alf[2][4], Bf[4][4];
            ldm_x4(Ahf[0], a0);
            ldm_x4(Ahf[1], a1);
            ldm_x4(Alf[0], a0 + TILE_B);
            ldm_x4(Alf[1], a1 + TILE_B);

            // Bh resident: passes Ah*Bh and Al*Bh
#pragma unroll
            for (int g = 0; g < 4; g++) ldm_x4(Bf[g], bA[g]);
#pragma unroll
            for (int g = 0; g < 4; g++)
#pragma unroll
                for (int h = 0; h < 2; h++)
#pragma unroll
                    for (int t = 0; t < 2; t++)
                        mma16816(acc[t][g * 2 + h], Ahf[t],
                                 Bf[g][h * 2], Bf[g][h * 2 + 1]);
#pragma unroll
            for (int g = 0; g < 4; g++)
#pragma unroll
                for (int h = 0; h < 2; h++)
#pragma unroll
                    for (int t = 0; t < 2; t++)
                        mma16816(acc[t][g * 2 + h], Alf[t],
                                 Bf[g][h * 2], Bf[g][h * 2 + 1]);
            // overwrite with Bl: pass Ah*Bl
#pragma unroll
            for (int g = 0; g < 4; g++) ldm_x4(Bf[g], bA[g] + TILE_B);
#pragma unroll
            for (int g = 0; g < 4; g++)
#pragma unroll
                for (int h = 0; h < 2; h++)
#pragma unroll
                    for (int t = 0; t < 2; t++)
                        mma16816(acc[t][g * 2 + h], Ahf[t],
                                 Bf[g][h * 2], Bf[g][h * 2 + 1]);
        }
        __syncthreads();
    }

    const int crow = bm + wm * 32 + (lane >> 2);
    const int ccol = bn + wn * 64 + (lane & 3) * 2;
#pragma unroll
    for (int t = 0; t < 2; t++) {
        const int r0 = crow + t * 16;
#pragma unroll
        for (int n = 0; n < 8; n++) {
            const int col = ccol + n * 8;
            float bx = 0.f, by = 0.f;
            if (bias) { bx = __ldg(bias + col); by = __ldg(bias + col + 1); }
            *reinterpret_cast<float2*>(&C[(size_t)r0 * N + col]) =
                make_float2(acc[t][n][0] + bx, acc[t][n][1] + by);
            *reinterpret_cast<float2*>(&C[(size_t)(r0 + 8) * N + col]) =
                make_float2(acc[t][n][2] + bx, acc[t][n][3] + by);
        }
    }
}

// ---------------------------------------------------------------------------
// Tiled local 5x5 attention, one head per block, CH=32 dims per stage.
// (Proven R10 version, unchanged.)
// Block = 256 threads = 16x16 pixel tile. Smem: dim-pair layout
// sm[16 pairs][20][21][2] -> conflict-free LDS.64 neighbor reads.
// Output written as bf16 hi/lo split (feeds GEMM2 directly).
// OOB halo entries zero -> logit contribution 0 (matches zero-padding).
// ---------------------------------------------------------------------------
#define ATT_SMEM (16 * 20 * 21 * 2 * 4)   // 53760 B
#define SIDX(p, hy, hx) ((((p) * 20 + (hy)) * 21 + (hx)) * 2)

__global__ void __launch_bounds__(256)
local_attn_tile(const float* __restrict__ qkv,
                __nv_bfloat16* __restrict__ oh,
                __nv_bfloat16* __restrict__ ol)
{
    extern __shared__ float smf[];

    const int tid  = threadIdx.x;
    const int px   = tid & 15;
    const int py   = tid >> 4;

    const int bid  = blockIdx.x;         // 0..511
    const int tx   = bid & 3;
    const int ty   = (bid >> 2) & 3;
    const int head = (bid >> 4) & 7;
    const int b    = bid >> 7;

    const int X = tx * 16 + px;
    const int Y = ty * 16 + py;
    const int r = b * 4096 + Y * 64 + X;

    const float* base  = qkv + (size_t)b * 4096 * QKV_N;
    const float* kbase = base + 512 + head * 64;
    const float* vbase = base + 1024 + head * 64;
    const float* qrow  = qkv + (size_t)r * QKV_N + head * 64;

    float dots[25];
#pragma unroll
    for (int f = 0; f < 25; f++) dots[f] = 0.f;

    // ---- Phase 1: logits, 2 chunks of 32 dims ----
    for (int jc = 0; jc < 2; jc++) {
        for (int s = tid; s < 3200; s += 256) {      // 400 rows x 8 granules
            const int row = s >> 3;
            const int q4  = s & 7;
            const int hy  = row / 20, hx = row - hy * 20;
            const int gy  = ty * 16 + hy - 2;
            const int gx  = tx * 16 + hx - 2;
            float4 v = make_float4(0.f, 0.f, 0.f, 0.f);
            if ((unsigned)gy < 64u && (unsigned)gx < 64u)
                v = *reinterpret_cast<const float4*>(
                    kbase + (size_t)(gy * 64 + gx) * QKV_N + jc * 32 + q4 * 4);
            *reinterpret_cast<float2*>(&smf[SIDX(2 * q4, hy, hx)]) =
                make_float2(v.x, v.y);
            *reinterpret_cast<float2*>(&smf[SIDX(2 * q4 + 1, hy, hx)]) =
                make_float2(v.z, v.w);
        }
        __syncthreads();

        float qs[32];
#pragma unroll
        for (int i = 0; i < 8; i++) {
            float4 qv = reinterpret_cast<const float4*>(qrow + jc * 32)[i];
            qs[4 * i] = qv.x; qs[4 * i + 1] = qv.y;
            qs[4 * i + 2] = qv.z; qs[4 * i + 3] = qv.w;
        }
#pragma unroll
        for (int p = 0; p < 16; p++) {
            const float q0 = qs[2 * p], q1 = qs[2 * p + 1];
#pragma unroll
            for (int dy = 0; dy < 5; dy++) {
#pragma unroll
                for (int dx = 0; dx < 5; dx++) {
                    const float2 kv = *reinterpret_cast<const float2*>(
                        &smf[SIDX(p, py + dy, px + dx)]);
                    dots[dy * 5 + dx] += q0 * kv.x + q1 * kv.y;
                }
            }
        }
        __syncthreads();
    }

    // ---- Softmax over 25 (per-thread) ----
    float m = -1e30f;
#pragma unroll
    for (int f = 0; f < 25; f++) {
        dots[f] *= 0.125f;                 // 64^-0.5
        m = fmaxf(m, dots[f]);
    }
    float s = 0.f;
#pragma unroll
    for (int f = 0; f < 25; f++) { dots[f] = __expf(dots[f] - m); s += dots[f]; }
    const float inv = 1.0f / s;
#pragma unroll
    for (int f = 0; f < 25; f++) dots[f] *= inv;

    // ---- Phase 2: weighted V, split-write bf16 hi/lo ----
    for (int jc = 0; jc < 2; jc++) {
        for (int s = tid; s < 3200; s += 256) {
            const int row = s >> 3;
            const int q4  = s & 7;
            const int hy  = row / 20, hx = row - hy * 20;
            const int gy  = ty * 16 + hy - 2;
            const int gx  = tx * 16 + hx - 2;
            float4 v = make_float4(0.f, 0.f, 0.f, 0.f);
            if ((unsigned)gy < 64u && (unsigned)gx < 64u)
                v = *reinterpret_cast<const float4*>(
                    vbase + (size_t)(gy * 64 + gx) * QKV_N + jc * 32 + q4 * 4);
            *reinterpret_cast<float2*>(&smf[SIDX(2 * q4, hy, hx)]) =
                make_float2(v.x, v.y);
            *reinterpret_cast<float2*>(&smf[SIDX(2 * q4 + 1, hy, hx)]) =
                make_float2(v.z, v.w);
        }
        __syncthreads();

        float o[32];
#pragma unroll
        for (int p = 0; p < 16; p++) {
            float o0 = 0.f, o1 = 0.f;
#pragma unroll
            for (int dy = 0; dy < 5; dy++) {
#pragma unroll
                for (int dx = 0; dx < 5; dx++) {
                    const float2 vv = *reinterpret_cast<const float2*>(
                        &smf[SIDX(p, py + dy, px + dx)]);
                    const float w = dots[dy * 5 + dx];
                    o0 += w * vv.x;
                    o1 += w * vv.y;
                }
            }
            o[2 * p] = o0;
            o[2 * p + 1] = o1;
        }

        __nv_bfloat162 hb[16], lb[16];
#pragma unroll
        for (int i = 0; i < 16; i++) {
            const float a = o[2 * i], c = o[2 * i + 1];
            const __nv_bfloat16 ha = __float2bfloat16_rn(a);
            const __nv_bfloat16 hc = __float2bfloat16_rn(c);
            hb[i].x = ha; hb[i].y = hc;
            lb[i].x = __float2bfloat16_rn(a - __bfloat162float(ha));
            lb[i].y = __float2bfloat16_rn(c - __bfloat162float(hc));
        }
        const size_t oo = (size_t)r * INNER + head * 64 + jc * 32;
        reinterpret_cast<uint4*>(oh + oo)[0] = reinterpret_cast<uint4*>(hb)[0];
        reinterpret_cast<uint4*>(oh + oo)[1] = reinterpret_cast<uint4*>(hb)[1];
        reinterpret_cast<uint4*>(oh + oo)[2] = reinterpret_cast<uint4*>(hb)[2];
        reinterpret_cast<uint4*>(oh + oo)[3] = reinterpret_cast<uint4*>(hb)[3];
        reinterpret_cast<uint4*>(ol + oo)[0] = reinterpret_cast<uint4*>(lb)[0];
        reinterpret_cast<uint4*>(ol + oo)[1] = reinterpret_cast<uint4*>(lb)[1];
        reinterpret_cast<uint4*>(ol + oo)[2] = reinterpret_cast<uint4*>(lb)[2];
        reinterpret_cast<uint4*>(ol + oo)[3] = reinterpret_cast<uint4*>(lb)[3];
        __syncthreads();
    }
}

// ---------------------------------------------------------------------------
// Launch
// ---------------------------------------------------------------------------
extern "C" void kernel_launch(void* const* d_in, const int* in_sizes, int n_in,
                              void* d_out, int out_size)
{
    const float* x     = (const float*)d_in[0];
    const float* w_qkv = (const float*)d_in[1];
    const float* w_out = (const float*)d_in[2];
    const float* b_out = (const float*)d_in[3];
    float* out = (float*)d_out;

    float *qkv;
    __nv_bfloat16 *xh, *xl, *wqh, *wql, *woh, *wol, *ah, *al;
    cudaGetSymbolAddress((void**)&qkv, g_qkv);
    cudaGetSymbolAddress((void**)&xh,  g_xh);
    cudaGetSymbolAddress((void**)&xl,  g_xl);
    cudaGetSymbolAddress((void**)&wqh, g_wqh);
    cudaGetSymbolAddress((void**)&wql, g_wql);
    cudaGetSymbolAddress((void**)&woh, g_woh);
    cudaGetSymbolAddress((void**)&wol, g_wol);
    cudaGetSymbolAddress((void**)&ah,  g_ah);
    cudaGetSymbolAddress((void**)&al,  g_al);

    cudaFuncSetAttribute(gemm_bf16,
                         cudaFuncAttributeMaxDynamicSharedMemorySize, GSMEM);
    cudaFuncSetAttribute(local_attn_tile,
                         cudaFuncAttributeMaxDynamicSharedMemorySize, ATT_SMEM);

    // Pre-split inputs to bf16 hi/lo
    split_bf16<<<(MROWS * DIMM / 4 + 255) / 256, 256>>>(x, xh, xl,
                                                        MROWS * DIMM / 4);
    split_bf16<<<(QKV_N * DIMM / 4 + 255) / 256, 256>>>(w_qkv, wqh, wql,
                                                        QKV_N * DIMM / 4);
    split_bf16<<<(DIMM * INNER / 4 + 255) / 256, 256>>>(w_out, woh, wol,
                                                        DIMM * INNER / 4);

    // GEMM1: qkv = x @ w_qkv^T   -> fp32 [16384,1536]
    dim3 g1(QKV_N / 128, MROWS / 128);
    gemm_bf16<<<g1, 256, GSMEM>>>(xh, xl, wqh, wql, nullptr, qkv, QKV_N);

    // Local attention -> bf16 hi/lo [16384,512]
    local_attn_tile<<<512, 256, ATT_SMEM>>>(qkv, ah, al);

    // GEMM2: out = att @ w_out^T + b_out -> fp32 [16384,512]
    dim3 g2(DIMM / 128, MROWS / 128);
    gemm_bf16<<<g2, 256, GSMEM>>>(ah, al, woh, wol, b_out, out, DIMM);
}

// round 15
// speedup vs baseline: 1.6838x; 1.0103x over previous
#include <cuda_runtime.h>
#include <cuda_bf16.h>
#include <cstdint>

// Problem constants (fixed by reference setup_inputs)
#define Bq     4
#define NPIX   4096          // 64*64
#define HEADS  8
#define HD     64
#define DIMM   512
#define INNER  512           // HEADS*HD
#define MROWS  (Bq*NPIX)     // 16384
#define QKV_N  (3*INNER)     // 1536

// Scratch (device globals — no runtime allocation allowed)
__device__ float         g_qkv[(size_t)MROWS * QKV_N];   // fp32 qkv (GEMM1 out)
__device__ __nv_bfloat16 g_xh[(size_t)MROWS * DIMM];     // x hi/lo
__device__ __nv_bfloat16 g_xl[(size_t)MROWS * DIMM];
__device__ __nv_bfloat16 g_wqh[(size_t)QKV_N * DIMM];    // w_qkv hi/lo
__device__ __nv_bfloat16 g_wql[(size_t)QKV_N * DIMM];
__device__ __nv_bfloat16 g_woh[(size_t)DIMM * INNER];    // w_out hi/lo
__device__ __nv_bfloat16 g_wol[(size_t)DIMM * INNER];
__device__ __nv_bfloat16 g_ah[(size_t)MROWS * INNER];    // att hi/lo
__device__ __nv_bfloat16 g_al[(size_t)MROWS * INNER];
__device__ float         g_zero[16];                     // never written: stays 0

// ---------------------------------------------------------------------------
// Primitives (base PTX only — must compile at compute_103)
// ---------------------------------------------------------------------------
__device__ __forceinline__ uint32_t smem_u32(const void* p) {
    uint32_t a;
    asm("{ .reg .u64 t; cvta.to.shared.u64 t, %1; cvt.u32.u64 %0, t; }"
        : "=r"(a) : "l"(p));
    return a;
}
__device__ __forceinline__ void ldm_x4(uint32_t* r, uint32_t addr) {
    asm volatile("ldmatrix.sync.aligned.m8n8.x4.shared.b16 {%0,%1,%2,%3}, [%4];"
                 : "=r"(r[0]), "=r"(r[1]), "=r"(r[2]), "=r"(r[3]) : "r"(addr));
}
__device__ __forceinline__ void mma16816(float* d, const uint32_t* a,
                                         uint32_t b0, uint32_t b1) {
    asm volatile(
        "mma.sync.aligned.m16n8k16.row.col.f32.bf16.bf16.f32 "
        "{%0,%1,%2,%3}, {%4,%5,%6,%7}, {%8,%9}, {%0,%1,%2,%3};"
        : "+f"(d[0]), "+f"(d[1]), "+f"(d[2]), "+f"(d[3])
        : "r"(a[0]), "r"(a[1]), "r"(a[2]), "r"(a[3]), "r"(b0), "r"(b1));
}
__device__ __forceinline__ void cp_async16(uint32_t dst, const void* src) {
    asm volatile("cp.async.cg.shared.global [%0], [%1], 16;"
                 :: "r"(dst), "l"(src));
}
__device__ __forceinline__ void cp_async8(uint32_t dst, const void* src) {
    asm volatile("cp.async.ca.shared.global [%0], [%1], 8;"
                 :: "r"(dst), "l"(src));
}
#define CP_COMMIT() asm volatile("cp.async.commit_group;" ::: "memory")
#define CP_WAIT1()  asm volatile("cp.async.wait_group 1;" ::: "memory")
#define CP_WAIT0()  asm volatile("cp.async.wait_group 0;" ::: "memory")

// ---------------------------------------------------------------------------
// fp32 -> bf16 hi/lo split (elementwise)
// ---------------------------------------------------------------------------
__global__ void __launch_bounds__(256)
split_bf16(const float* __restrict__ in, __nv_bfloat16* __restrict__ hi,
           __nv_bfloat16* __restrict__ lo, int n4)
{
    const int i = blockIdx.x * 256 + threadIdx.x;
    if (i >= n4) return;
    float4 f = reinterpret_cast<const float4*>(in)[i];
    __nv_bfloat162 h[2], l[2];
    const float fs[4] = {f.x, f.y, f.z, f.w};
#pragma unroll
    for (int j = 0; j < 2; j++) {
        const float a = fs[2 * j], b = fs[2 * j + 1];
        const __nv_bfloat16 ha = __float2bfloat16_rn(a);
        const __nv_bfloat16 hb = __float2bfloat16_rn(b);
        h[j].x = ha; h[j].y = hb;
        l[j].x = __float2bfloat16_rn(a - __bfloat162float(ha));
        l[j].y = __float2bfloat16_rn(b - __bfloat162float(hb));
    }
    reinterpret_cast<uint2*>(hi)[i] = *reinterpret_cast<uint2*>(h);
    reinterpret_cast<uint2*>(lo)[i] = *reinterpret_cast<uint2*>(l);
}

// ---------------------------------------------------------------------------
// bf16-split GEMM, pre-converted operands. Single 64KB stage, 2 CTAs/SM.
// (Proven R13 version, unchanged.)
// C[M,N] = A[M,512] @ B[N,512]^T (+bias); D = Ah*Bh + Al*Bh + Ah*Bl.
// ---------------------------------------------------------------------------
#define TILE_B   16384
#define GSMEM    65536

__global__ void __launch_bounds__(256, 2)
gemm_bf16(const __nv_bfloat16* __restrict__ Ah,
          const __nv_bfloat16* __restrict__ Al,
          const __nv_bfloat16* __restrict__ Bh,
          const __nv_bfloat16* __restrict__ Bl,
          const float* __restrict__ bias, float* __restrict__ C, int N)
{
    extern __shared__ char smem[];
    const uint32_t sbase = smem_u32(smem);
    const int tid  = threadIdx.x;
    const int wid  = tid >> 5;
    const int lane = tid & 31;
    const int wm   = wid & 3;
    const int wn   = wid >> 2;
    const int bn   = blockIdx.x * 128;
    const int bm   = blockIdx.y * 128;

    uint32_t aAddr[2];
    {
        const int rlo = lane & 15;
        const int sub = (lane >> 4) * 16;
#pragma unroll
        for (int t = 0; t < 2; t++) {
            const int row = wm * 32 + t * 16 + rlo;
            aAddr[t] = sbase + row * 128 + (uint32_t)(sub ^ ((row & 7) << 4));
        }
    }
    uint32_t bAddr[4];
    {
        const int nlo = (lane & 7) + ((lane & 16) >> 1);
        const int sub = (lane & 8) << 1;
#pragma unroll
        for (int g = 0; g < 4; g++) {
            const int row = wn * 64 + g * 16 + nlo;
            bAddr[g] = sbase + 32768 + row * 128
                     + (uint32_t)(sub ^ ((row & 7) << 4));
        }
    }

    float acc[2][8][4];
#pragma unroll
    for (int t = 0; t < 2; t++)
#pragma unroll
        for (int n = 0; n < 8; n++)
#pragma unroll
            for (int j = 0; j < 4; j++) acc[t][n][j] = 0.f;

    for (int c = 0; c < 8; c++) {
        {
            const int k0 = c * 64;
#pragma unroll
            for (int i = 0; i < 4; i++) {
                const int idx = tid + 256 * i;           // 0..1023
                const int row = idx >> 3;
                const int g   = idx & 7;
                const uint32_t off =
                    (uint32_t)((row * 128 + g * 16) ^ ((row & 7) << 4));
                const size_t ao = (size_t)(bm + row) * 512 + k0 + g * 8;
                const size_t bo = (size_t)(bn + row) * 512 + k0 + g * 8;
                cp_async16(sbase + off,         Ah + ao);
                cp_async16(sbase + 16384 + off, Al + ao);
                cp_async16(sbase + 32768 + off, Bh + bo);
                cp_async16(sbase + 49152 + off, Bl + bo);
            }
        }
        CP_COMMIT();
        CP_WAIT0();
        __syncthreads();

#pragma unroll
        for (int ks = 0; ks < 4; ks++) {
            uint32_t a0 = aAddr[0], a1 = aAddr[1];
            uint32_t bA[4];
#pragma unroll
            for (int g = 0; g < 4; g++) bA[g] = bAddr[g];
            {
                const int subA = (lane >> 4) * 16;
                const int subB = (lane & 8) << 1;
                const int kso  = ks * 32;
#pragma unroll
                for (int t = 0; t < 2; t++) {
                    const int row = wm * 32 + t * 16 + (lane & 15);
                    const uint32_t mask = (row & 7) << 4;
                    const uint32_t adj = ((uint32_t)(subA + kso) ^ mask)
                                       - ((uint32_t)subA ^ mask);
                    if (t == 0) a0 += adj; else a1 += adj;
                }
                const int nlo = (lane & 7) + ((lane & 16) >> 1);
#pragma unroll
                for (int g = 0; g < 4; g++) {
                    const int row = wn * 64 + g * 16 + nlo;
                    const uint32_t mask = (row & 7) << 4;
                    bA[g] += ((uint32_t)(subB + kso) ^ mask)
                           - ((uint32_t)subB ^ mask);
                }
            }

            uint32_t Ahf[2][4], Alf[2][4], Bf[4][4];
            ldm_x4(Ahf[0], a0);
            ldm_x4(Ahf[1], a1);
            ldm_x4(Alf[0], a0 + TILE_B);
            ldm_x4(Alf[1], a1 + TILE_B);

#pragma unroll
            for (int g = 0; g < 4; g++) ldm_x4(Bf[g], bA[g]);
#pragma unroll
            for (int g = 0; g < 4; g++)
#pragma unroll
                for (int h = 0; h < 2; h++)
#pragma unroll
                    for (int t = 0; t < 2; t++)
                        mma16816(acc[t][g * 2 + h], Ahf[t],
                                 Bf[g][h * 2], Bf[g][h * 2 + 1]);
#pragma unroll
            for (int g = 0; g < 4; g++)
#pragma unroll
                for (int h = 0; h < 2; h++)
#pragma unroll
                    for (int t = 0; t < 2; t++)
                        mma16816(acc[t][g * 2 + h], Alf[t],
                                 Bf[g][h * 2], Bf[g][h * 2 + 1]);
#pragma unroll
            for (int g = 0; g < 4; g++) ldm_x4(Bf[g], bA[g] + TILE_B);
#pragma unroll
            for (int g = 0; g < 4; g++)
#pragma unroll
                for (int h = 0; h < 2; h++)
#pragma unroll
                    for (int t = 0; t < 2; t++)
                        mma16816(acc[t][g * 2 + h], Ahf[t],
                                 Bf[g][h * 2], Bf[g][h * 2 + 1]);
        }
        __syncthreads();
    }

    const int crow = bm + wm * 32 + (lane >> 2);
    const int ccol = bn + wn * 64 + (lane & 3) * 2;
#pragma unroll
    for (int t = 0; t < 2; t++) {
        const int r0 = crow + t * 16;
#pragma unroll
        for (int n = 0; n < 8; n++) {
            const int col = ccol + n * 8;
            float bx = 0.f, by = 0.f;
            if (bias) { bx = __ldg(bias + col); by = __ldg(bias + col + 1); }
            *reinterpret_cast<float2*>(&C[(size_t)r0 * N + col]) =
                make_float2(acc[t][n][0] + bx, acc[t][n][1] + by);
            *reinterpret_cast<float2*>(&C[(size_t)(r0 + 8) * N + col]) =
                make_float2(acc[t][n][2] + bx, acc[t][n][3] + by);
        }
    }
}

// ---------------------------------------------------------------------------
// Tiled local 5x5 attention, cp.async double-buffered, CH=16 dims/chunk.
// Block = 256 threads = 16x16 pixel tile; 8 chunks (4 k, 4 v).
// OOB halo rows redirect the cp.async SOURCE POINTER to g_zero (fixed 8B
// copies, no runtime-size operand) -> exact zero-pad semantics.
// Dim-pair smem layout: conflict-free LDS.64 neighbor reads.
// Output written as bf16 hi/lo split (feeds GEMM2 directly).
// ---------------------------------------------------------------------------
#define ACH        16
#define AST_FL     (8 * 20 * 21 * 2)           // floats per stage = 6720
#define ATT_SMEM   (2 * AST_FL * 4)            // 53760 B
#define SIDX(p, hy, hx) ((((p) * 20 + (hy)) * 21 + (hx)) * 2)

__global__ void __launch_bounds__(256)
local_attn_tile(const float* __restrict__ qkv,
                __nv_bfloat16* __restrict__ oh,
                __nv_bfloat16* __restrict__ ol)
{
    extern __shared__ float smf[];
    const uint32_t sbase = smem_u32(smf);

    const int tid  = threadIdx.x;
    const int px   = tid & 15;
    const int py   = tid >> 4;

    const int bid  = blockIdx.x;         // 0..511
    const int tx   = bid & 3;
    const int ty   = (bid >> 2) & 3;
    const int head = (bid >> 4) & 7;
    const int b    = bid >> 7;

    const int X = tx * 16 + px;
    const int Y = ty * 16 + py;
    const int r = b * 4096 + Y * 64 + X;

    const float* base  = qkv + (size_t)b * 4096 * QKV_N;
    const float* kbase = base + 512 + head * 64;
    const float* vbase = base + 1024 + head * 64;
    const float* qrow  = qkv + (size_t)r * QKV_N + head * 64;

    // stage chunk ch (0..3 = k dims ch*16, 4..7 = v dims (ch-4)*16)
    auto prefetch = [&](int stage, int ch) {
        const float* src0 = (ch < 4) ? kbase + ch * ACH
                                     : vbase + (ch - 4) * ACH;
        const uint32_t sb = sbase + (uint32_t)(stage * AST_FL * 4);
#pragma unroll
        for (int i = 0; i < 13; i++) {           // ceil(3200/256) = 13
            const int s = tid + 256 * i;
            if (s >= 3200) break;
            const int row = s >> 3;              // 0..399
            const int p   = s & 7;               // dim-pair 0..7
            const int hy  = row / 20, hx = row - hy * 20;
            const int gy  = ty * 16 + hy - 2;
            const int gx  = tx * 16 + hx - 2;
            const bool ok = ((unsigned)gy < 64u) && ((unsigned)gx < 64u);
            const float* src = ok
                ? src0 + (size_t)(gy * 64 + gx) * QKV_N + p * 2
                : (const float*)g_zero;
            cp_async8(sb + (uint32_t)(SIDX(p, hy, hx) * 4), src);
        }
    };

    float dots[25];
#pragma unroll
    for (int f = 0; f < 25; f++) dots[f] = 0.f;

    prefetch(0, 0);
    CP_COMMIT();

    for (int c = 0; c < 8; c++) {
        if (c < 7) {
            prefetch((c + 1) & 1, c + 1);
            CP_COMMIT();
            CP_WAIT1();
        } else {
            CP_WAIT0();
        }
        __syncthreads();

        const float* st = smf + (c & 1) * AST_FL;

        if (c < 4) {
            // logits chunk
            float qs[ACH];
#pragma unroll
            for (int i = 0; i < 4; i++) {
                float4 qv = reinterpret_cast<const float4*>(qrow + c * ACH)[i];
                qs[4 * i] = qv.x; qs[4 * i + 1] = qv.y;
                qs[4 * i + 2] = qv.z; qs[4 * i + 3] = qv.w;
            }
#pragma unroll
            for (int p = 0; p < 8; p++) {
                const float q0 = qs[2 * p], q1 = qs[2 * p + 1];
#pragma unroll
                for (int dy = 0; dy < 5; dy++) {
#pragma unroll
                    for (int dx = 0; dx < 5; dx++) {
                        const float2 kv = *reinterpret_cast<const float2*>(
                            &st[SIDX(p, py + dy, px + dx)]);
                        dots[dy * 5 + dx] += q0 * kv.x + q1 * kv.y;
                    }
                }
            }
            if (c == 3) {
                // softmax over 25 (per-thread)
                float m = -1e30f;
#pragma unroll
                for (int f = 0; f < 25; f++) {
                    dots[f] *= 0.125f;             // 64^-0.5
                    m = fmaxf(m, dots[f]);
                }
                float s = 0.f;
#pragma unroll
                for (int f = 0; f < 25; f++) {
                    dots[f] = __expf(dots[f] - m);
                    s += dots[f];
                }
                const float inv = 1.0f / s;
#pragma unroll
                for (int f = 0; f < 25; f++) dots[f] *= inv;
            }
        } else {
            // weighted-V chunk
            const int jc = c - 4;
            float o[ACH];
#pragma unroll
            for (int p = 0; p < 8; p++) {
                float o0 = 0.f, o1 = 0.f;
#pragma unroll
                for (int dy = 0; dy < 5; dy++) {
#pragma unroll
                    for (int dx = 0; dx < 5; dx++) {
                        const float2 vv = *reinterpret_cast<const float2*>(
                            &st[SIDX(p, py + dy, px + dx)]);
                        const float w = dots[dy * 5 + dx];
                        o0 += w * vv.x;
                        o1 += w * vv.y;
                    }
                }
                o[2 * p] = o0;
                o[2 * p + 1] = o1;
            }
            __nv_bfloat162 hb[8], lb[8];
#pragma unroll
            for (int i = 0; i < 8; i++) {
                const float a = o[2 * i], d = o[2 * i + 1];
                const __nv_bfloat16 ha = __float2bfloat16_rn(a);
                const __nv_bfloat16 hd = __float2bfloat16_rn(d);
                hb[i].x = ha; hb[i].y = hd;
                lb[i].x = __float2bfloat16_rn(a - __bfloat162float(ha));
                lb[i].y = __float2bfloat16_rn(d - __bfloat162float(hd));
            }
            const size_t oo = (size_t)r * INNER + head * 64 + jc * ACH;
            reinterpret_cast<uint4*>(oh + oo)[0] =
                reinterpret_cast<uint4*>(hb)[0];
            reinterpret_cast<uint4*>(oh + oo)[1] =
                reinterpret_cast<uint4*>(hb)[1];
            reinterpret_cast<uint4*>(ol + oo)[0] =
                reinterpret_cast<uint4*>(lb)[0];
            reinterpret_cast<uint4*>(ol + oo)[1] =
                reinterpret_cast<uint4*>(lb)[1];
        }
        __syncthreads();
    }
}

// ---------------------------------------------------------------------------
// Launch
// ---------------------------------------------------------------------------
extern "C" void kernel_launch(void* const* d_in, const int* in_sizes, int n_in,
                              void* d_out, int out_size)
{
    const float* x     = (const float*)d_in[0];
    const float* w_qkv = (const float*)d_in[1];
    const float* w_out = (const float*)d_in[2];
    const float* b_out = (const float*)d_in[3];
    float* out = (float*)d_out;

    float *qkv;
    __nv_bfloat16 *xh, *xl, *wqh, *wql, *woh, *wol, *ah, *al;
    cudaGetSymbolAddress((void**)&qkv, g_qkv);
    cudaGetSymbolAddress((void**)&xh,  g_xh);
    cudaGetSymbolAddress((void**)&xl,  g_xl);
    cudaGetSymbolAddress((void**)&wqh, g_wqh);
    cudaGetSymbolAddress((void**)&wql, g_wql);
    cudaGetSymbolAddress((void**)&woh, g_woh);
    cudaGetSymbolAddress((void**)&wol, g_wol);
    cudaGetSymbolAddress((void**)&ah,  g_ah);
    cudaGetSymbolAddress((void**)&al,  g_al);

    cudaFuncSetAttribute(gemm_bf16,
                         cudaFuncAttributeMaxDynamicSharedMemorySize, GSMEM);
    cudaFuncSetAttribute(local_attn_tile,
                         cudaFuncAttributeMaxDynamicSharedMemorySize, ATT_SMEM);

    // Pre-split inputs to bf16 hi/lo
    split_bf16<<<(MROWS * DIMM / 4 + 255) / 256, 256>>>(x, xh, xl,
                                                        MROWS * DIMM / 4);
    split_bf16<<<(QKV_N * DIMM / 4 + 255) / 256, 256>>>(w_qkv, wqh, wql,
                                                        QKV_N * DIMM / 4);
    split_bf16<<<(DIMM * INNER / 4 + 255) / 256, 256>>>(w_out, woh, wol,
                                                        DIMM * INNER / 4);

    // GEMM1: qkv = x @ w_qkv^T   -> fp32 [16384,1536]
    dim3 g1(QKV_N / 128, MROWS / 128);
    gemm_bf16<<<g1, 256, GSMEM>>>(xh, xl, wqh, wql, nullptr, qkv, QKV_N);

    // Local attention -> bf16 hi/lo [16384,512]
    local_attn_tile<<<512, 256, ATT_SMEM>>>(qkv, ah, al);

    // GEMM2: out = att @ w_out^T + b_out -> fp32 [16384,512]
    dim3 g2(DIMM / 128, MROWS / 128);
    gemm_bf16<<<g2, 256, GSMEM>>>(ah, al, woh, wol, b_out, out, DIMM);
}